// round 5
// baseline (speedup 1.0000x reference)
#include <cuda_runtime.h>
#include <cstdint>

// Problem constants
#define BN   8
#define CN   256
#define HN   64
#define WN   64
#define GN   4
#define KKN  9
#define CG   64
#define OCF  108
#define OCP  128      // padded offset-conv out channels
#define HWN  (HN*WN)

// ---------------------------------------------------------------------------
// Scratch
// ---------------------------------------------------------------------------
__device__ float g_off[BN*OCF*HWN];          // offset/mask conv output
__device__ float g_out[BN*CN*HWN];           // DCN conv output (pre-LN)
__device__ float g_wT [GN*KKN*CG*CG];        // w_dcn as [g][k][oc][c], tf32-rounded
__device__ float g_wA [8*KKN*OCP*32];        // w_off as [cc][kk][oc 128][c 32], tf32-rounded
__device__ float g_xT [BN*GN*HWN*CG];        // x transposed: [b][g][px][c]

// ---------------------------------------------------------------------------
// helpers
// ---------------------------------------------------------------------------
__device__ __forceinline__ float tf32r(float v) {
    uint32_t u; asm("cvt.rna.tf32.f32 %0, %1;" : "=r"(u) : "f"(v));
    return __uint_as_float(u);
}
__device__ __forceinline__ void mma_tf32(float* d, const uint32_t* a,
                                         uint32_t b0, uint32_t b1) {
    asm volatile(
        "mma.sync.aligned.m16n8k8.row.col.f32.tf32.tf32.f32 "
        "{%0,%1,%2,%3}, {%4,%5,%6,%7}, {%8,%9}, {%0,%1,%2,%3};"
        : "+f"(d[0]), "+f"(d[1]), "+f"(d[2]), "+f"(d[3])
        : "r"(a[0]), "r"(a[1]), "r"(a[2]), "r"(a[3]), "r"(b0), "r"(b1));
}

// ---------------------------------------------------------------------------
// Kernel 0a: w_dcn [256][64][3][3] -> g_wT[g][k][oc][c] (tf32-rounded)
// ---------------------------------------------------------------------------
__global__ void __launch_bounds__(256) transpose_wdcn_k(const float* __restrict__ w_dcn)
{
    int i = blockIdx.x * 256 + threadIdx.x;
    if (i < GN*KKN*CG*CG) {
        int c  = i & 63;
        int oc = (i >> 6) & 63;
        int gk = i >> 12;
        int k  = gk % 9;
        int g  = gk / 9;
        g_wT[i] = tf32r(w_dcn[((g*CG + oc)*CG + c)*KKN + k]);
    }
}

// ---------------------------------------------------------------------------
// Kernel 0b: w_off -> g_wA[cc][kk][oc(128 pad)][c 32] (tf32-rounded)
// ---------------------------------------------------------------------------
__global__ void __launch_bounds__(256) prep_wA_k(const float* __restrict__ w_off)
{
    int i = blockIdx.x * 256 + threadIdx.x;
    if (i >= 8*KKN*OCP*32) return;
    int tile = i >> 12;
    int r    = i & 4095;
    int oc   = r >> 5;
    int c    = r & 31;
    int kk   = tile % 9;
    int cc   = tile / 9;
    float w = 0.f;
    if (oc < OCF) w = tf32r(w_off[(oc*CN + cc*32 + c)*KKN + kk]);
    g_wA[i] = w;
}

// ---------------------------------------------------------------------------
// Kernel 0c: transpose x per (b,g): [64c][4096px] -> g_xT [4096px][64c]
// grid (HWN/32, CG/32, BN*GN), block (32,8)
// ---------------------------------------------------------------------------
__global__ void __launch_bounds__(256) transpose_x_k(const float* __restrict__ x)
{
    __shared__ float tile[32][33];
    const int bg = blockIdx.z;
    const int p0 = blockIdx.x * 32;
    const int c0 = blockIdx.y * 32;
    const int tx = threadIdx.x, ty = threadIdx.y;
    const float* src = x + bg*CG*HWN;
#pragma unroll
    for (int i = 0; i < 32; i += 8)
        tile[ty + i][tx] = src[(c0 + ty + i)*HWN + p0 + tx];
    __syncthreads();
    float* dst = g_xT + (size_t)bg*HWN*CG;
#pragma unroll
    for (int i = 0; i < 32; i += 8)
        dst[(p0 + ty + i)*CG + c0 + tx] = tile[tx][ty + i];
}

// ---------------------------------------------------------------------------
// Kernel 1: offset/mask conv via mma.sync tf32, double-buffered weight tile.
// grid (HN/2, BN), block 256 (8 warps). Block: 2 rows x 64 px x 128 oc(pad).
// smem (floats): patch [32c][4r][66] pitch264 @0 (8448); Wt[2][128oc][36] @8448
// ---------------------------------------------------------------------------
#define OFC_WT     8448
#define OFC_FLOATS (OFC_WT + 2*OCP*36)

__global__ void __launch_bounds__(256, 2) offset_conv_mma_k(
    const float* __restrict__ x, const float* __restrict__ b_off)
{
    extern __shared__ float sm[];
    float* patch = sm;
    const uint32_t* PU = (const uint32_t*)patch;

    const int h0  = blockIdx.x * 2;
    const int b   = blockIdx.y;
    const int t   = threadIdx.x;
    const int lane = t & 31;
    const int wid = t >> 5;
    const int lm4 = lane & 3;
    const int ld4 = lane >> 2;
    const int mg  = wid & 3;
    const int ng  = wid >> 2;

    float D[2][8][4];
#pragma unroll
    for (int s = 0; s < 2; s++)
#pragma unroll
        for (int n = 0; n < 8; n++)
#pragma unroll
            for (int i = 0; i < 4; i++) D[s][n][i] = 0.f;

    int idx = 0;
    for (int cc = 0; cc < 8; cc++) {
        __syncthreads();      // prior mma done reading patch
        for (int i = t; i < 32*4*66; i += 256) {
            int c   = i / 264;
            int rem = i - c*264;
            int r   = rem / 66;
            int col = rem - r*66;
            int y   = h0 - 1 + r;
            int xx  = col - 1;
            float v = 0.f;
            if (y >= 0 && y < HN && xx >= 0 && xx < WN)
                v = x[((b*CN + cc*32 + c)*HN + y)*WN + xx];
            patch[c*264 + r*66 + col] = tf32r(v);
        }
        for (int kk = 0; kk < KKN; kk++, idx++) {
            float* Wb = sm + OFC_WT + (idx & 1)*OCP*36;
            const uint32_t* WtU = (const uint32_t*)Wb;
            // stage Wt tile [128][32] -> [128][36] (buffer idx&1)
            {
                const float4* src = (const float4*)(g_wA + (cc*9 + kk)*4096);
                for (int i = t; i < 1024; i += 256) {
                    float4 v = src[i];
                    int oc = i >> 3, c4 = (i & 7) * 4;
                    *reinterpret_cast<float4*>(&Wb[oc*36 + c4]) = v;
                }
            }
            __syncthreads();

            const int ky = kk / 3, kx = kk - (kk/3)*3;
            const int rbase = (ng + ky)*66 + kx + ld4;
#pragma unroll
            for (int step = 0; step < 4; step++) {
                const int k0 = step*8;
                uint32_t a[2][4];
#pragma unroll
                for (int s = 0; s < 2; s++) {
                    int ro = (mg*32 + s*16 + ld4)*36 + k0 + lm4;
                    a[s][0] = WtU[ro];
                    a[s][1] = WtU[ro + 8*36];
                    a[s][2] = WtU[ro + 4];
                    a[s][3] = WtU[ro + 8*36 + 4];
                }
                const int bb = (k0 + lm4)*264 + rbase;
#pragma unroll
                for (int nt = 0; nt < 8; nt++) {
                    uint32_t b0 = PU[bb + nt*8];
                    uint32_t b1 = PU[bb + nt*8 + 4*264];
                    mma_tf32(D[0][nt], a[0], b0, b1);
                    mma_tf32(D[1][nt], a[1], b0, b1);
                }
            }
        }
    }

    const int h = h0 + ng;
#pragma unroll
    for (int s = 0; s < 2; s++) {
#pragma unroll
        for (int nt = 0; nt < 8; nt++) {
            int ocA = mg*32 + s*16 + ld4;
            int ocB = ocA + 8;
            int w   = nt*8 + lm4*2;
            if (ocA < OCF) {
                float bo = b_off[ocA];
                *reinterpret_cast<float2*>(&g_off[((b*OCF + ocA)*HN + h)*WN + w])
                    = make_float2(D[s][nt][0] + bo, D[s][nt][1] + bo);
            }
            if (ocB < OCF) {
                float bo = b_off[ocB];
                *reinterpret_cast<float2*>(&g_off[((b*OCF + ocB)*HN + h)*WN + w])
                    = make_float2(D[s][nt][2] + bo, D[s][nt][3] + bo);
            }
        }
    }
}

// ---------------------------------------------------------------------------
// Kernel 2: deformable sampling + grouped conv, float4 gather from g_xT.
// grid (HN/4, GN, BN), block 256 (8 warps). Block: 4 rows x 64 px x 64 oc.
// smem (floats): S [256 px][68] @0 (17408); Wsm [64oc][68] @17408 (4352)
// ---------------------------------------------------------------------------
#define DCN_W      17408
#define DCN_FLOATS (DCN_W + CG*68)

__global__ void __launch_bounds__(256, 2) dcn_mma_k(
    const float* __restrict__ b_dcn)
{
    extern __shared__ float sm[];
    float* S   = sm;
    float* Wsm = sm + DCN_W;
    const uint32_t* SU = (const uint32_t*)S;
    const uint32_t* WU = (const uint32_t*)Wsm;

    const int h0 = blockIdx.x * 4;
    const int g  = blockIdx.y;
    const int b  = blockIdx.z;
    const int t  = threadIdx.x;
    const int lane = t & 31;
    const int wid = t >> 5;
    const int lm4 = lane & 3;
    const int ld4 = lane >> 2;
    const int mg  = wid & 1;          // oc base mg*32
    const int ng  = wid >> 1;         // px row (0..3)

    const int pxA = t;                // pixel owned by this thread
    const int hA  = h0 + (t >> 6);
    const int wA  = t & 63;
    const float* xt = g_xT + (size_t)(b*GN + g)*HWN*CG;

    float D[2][8][4];
#pragma unroll
    for (int s = 0; s < 2; s++)
#pragma unroll
        for (int n = 0; n < 8; n++)
#pragma unroll
            for (int i = 0; i < 4; i++) D[s][n][i] = 0.f;

    for (int k = 0; k < KKN; k++) {
        __syncthreads();   // previous mma done reading S/Wsm
        // ---- bilinear corner data (registers) ----
        int i0, i1, i2, i3; float w0, w1, w2, w3;
        {
            int ky = k / 3 - 1;
            int kx = k - (k/3)*3 - 1;
            int sp = hA*WN + wA;
            const float* ob = g_off + b*OCF*HWN;
            float oy = ob[((g*KKN + k)*2    )*HWN + sp];
            float ox = ob[((g*KKN + k)*2 + 1)*HWN + sp];
            float mz = ob[(2*GN*KKN + g*KKN + k)*HWN + sp];
            float mk = 1.f / (1.f + expf(-mz));
            float py  = (float)(hA + ky) + oy;
            float pxx = (float)(wA + kx) + ox;
            float y0f = floorf(py),  x0f = floorf(pxx);
            float wy1 = py - y0f,    wx1 = pxx - x0f;
            float wy0 = 1.f - wy1,   wx0 = 1.f - wx1;
            int y0 = (int)y0f, x0i = (int)x0f;
            int y1 = y0 + 1,   x1i = x0i + 1;
            bool vy0 = (y0 >= 0) & (y0 < HN);
            bool vy1 = (y1 >= 0) & (y1 < HN);
            bool vx0 = (x0i >= 0) & (x0i < WN);
            bool vx1 = (x1i >= 0) & (x1i < WN);
            int y0c = min(max(y0, 0), HN-1), y1c = min(max(y1, 0), HN-1);
            int x0c = min(max(x0i,0), WN-1), x1c = min(max(x1i,0), WN-1);
            i0 = y0c*WN + x0c;  i1 = y0c*WN + x1c;
            i2 = y1c*WN + x0c;  i3 = y1c*WN + x1c;
            w0 = (vy0 && vx0) ? wy0*wx0*mk : 0.f;
            w1 = (vy0 && vx1) ? wy0*wx1*mk : 0.f;
            w2 = (vy1 && vx0) ? wy1*wx0*mk : 0.f;
            w3 = (vy1 && vx1) ? wy1*wx1*mk : 0.f;
        }
        // ---- stage weight tile [64 oc][64 c] -> Wsm[oc*68 + c] ----
        {
            const float* wt = g_wT + (g*KKN + k)*CG*CG;
            for (int i = t; i < CG*CG; i += 256)
                Wsm[(i >> 6)*68 + (i & 63)] = wt[i];
        }
        // ---- gather: S[pxA][c] via float4 over channels ----
        {
            const float4* p0 = (const float4*)(xt + i0*CG);
            const float4* p1 = (const float4*)(xt + i1*CG);
            const float4* p2 = (const float4*)(xt + i2*CG);
            const float4* p3 = (const float4*)(xt + i3*CG);
            float* srow = S + pxA*68;
#pragma unroll
            for (int c4 = 0; c4 < 16; c4++) {
                float4 A = p0[c4], Bv = p1[c4], Cv = p2[c4], Dv = p3[c4];
                float4 v;
                v.x = tf32r(w0*A.x + w1*Bv.x + w2*Cv.x + w3*Dv.x);
                v.y = tf32r(w0*A.y + w1*Bv.y + w2*Cv.y + w3*Dv.y);
                v.z = tf32r(w0*A.z + w1*Bv.z + w2*Cv.z + w3*Dv.z);
                v.w = tf32r(w0*A.w + w1*Bv.w + w2*Cv.w + w3*Dv.w);
                *reinterpret_cast<float4*>(srow + c4*4) = v;
            }
        }
        __syncthreads();

        // ---- mma: K=64 -> 8 k8-steps.  B[k][n] = S[n][k] (px-major) ----
#pragma unroll
        for (int step = 0; step < 8; step++) {
            const int k0 = step*8;
            uint32_t a[2][4];
#pragma unroll
            for (int s = 0; s < 2; s++) {
                int ro = (mg*32 + s*16 + ld4)*68 + k0 + lm4;
                a[s][0] = WU[ro];
                a[s][1] = WU[ro + 8*68];
                a[s][2] = WU[ro + 4];
                a[s][3] = WU[ro + 8*68 + 4];
            }
            const int nb = (ng*64 + ld4)*68 + k0 + lm4;
#pragma unroll
            for (int nt = 0; nt < 8; nt++) {
                uint32_t b0 = SU[nb + nt*8*68];
                uint32_t b1 = SU[nb + nt*8*68 + 4];
                mma_tf32(D[0][nt], a[0], b0, b1);
                mma_tf32(D[1][nt], a[1], b0, b1);
            }
        }
    }

    // ---- epilogue: +bias, store ----
    const int h = h0 + ng;
#pragma unroll
    for (int s = 0; s < 2; s++) {
#pragma unroll
        for (int nt = 0; nt < 8; nt++) {
            int ocA = g*CG + mg*32 + s*16 + ld4;
            int ocB = ocA + 8;
            int w   = nt*8 + lm4*2;
            float boA = b_dcn[ocA], boB = b_dcn[ocB];
            *reinterpret_cast<float2*>(&g_out[((b*CN + ocA)*HN + h)*WN + w])
                = make_float2(D[s][nt][0] + boA, D[s][nt][1] + boA);
            *reinterpret_cast<float2*>(&g_out[((b*CN + ocB)*HN + h)*WN + w])
                = make_float2(D[s][nt][2] + boB, D[s][nt][3] + boB);
        }
    }
}

// ---------------------------------------------------------------------------
// Kernel 3: LayerNorm over C + sigmoid + gate
// ---------------------------------------------------------------------------
__global__ void __launch_bounds__(256) ln_gate_k(
    const float* __restrict__ x, const float* __restrict__ gamma,
    const float* __restrict__ beta, float* __restrict__ out)
{
    __shared__ float tile[CN][32];
    __shared__ float rs[8][32];
    __shared__ float rq[8][32];
    __shared__ float smu[32], srinv[32];

    const int b    = blockIdx.y;
    const int h    = blockIdx.x >> 1;
    const int wseg = (blockIdx.x & 1) * 32;
    const int t    = threadIdx.x;
    const int base = b*CN*HWN + h*WN + wseg;

    for (int i = t; i < CN*32; i += 256) {
        int c = i >> 5, p = i & 31;
        tile[c][p] = g_out[base + c*HWN + p];
    }
    __syncthreads();
    {
        int p = t & 31, part = t >> 5;
        float s = 0.f, q = 0.f;
        for (int c = part; c < CN; c += 8) {
            float v = tile[c][p];
            s += v; q += v*v;
        }
        rs[part][p] = s; rq[part][p] = q;
    }
    __syncthreads();
    if (t < 32) {
        float s = 0.f, q = 0.f;
#pragma unroll
        for (int part = 0; part < 8; part++) { s += rs[part][t]; q += rq[part][t]; }
        float mu  = s * (1.f/CN);
        float var = fmaxf(q * (1.f/CN) - mu*mu, 0.f);
        smu[t]   = mu;
        srinv[t] = rsqrtf(var + 1e-5f);
    }
    __syncthreads();
    for (int i = t; i < CN*32; i += 256) {
        int c = i >> 5, p = i & 31;
        float z = (tile[c][p] - smu[p]) * srinv[p] * gamma[c] + beta[c];
        float a = 1.f / (1.f + expf(-z));
        int idx = base + c*HWN + p;
        out[idx] = x[idx] * a;
    }
}

// ---------------------------------------------------------------------------
// Entry point
// ---------------------------------------------------------------------------
extern "C" void kernel_launch(void* const* d_in, const int* in_sizes, int n_in,
                              void* d_out, int out_size)
{
    const float* x     = (const float*)d_in[0];
    const float* w_off = (const float*)d_in[1];
    const float* b_off = (const float*)d_in[2];
    const float* w_dcn = (const float*)d_in[3];
    const float* b_dcn = (const float*)d_in[4];
    const float* gamma = (const float*)d_in[5];
    const float* beta  = (const float*)d_in[6];
    float* out = (float*)d_out;

    (void)in_sizes; (void)n_in; (void)out_size;

    cudaFuncSetAttribute(offset_conv_mma_k, cudaFuncAttributeMaxDynamicSharedMemorySize,
                         OFC_FLOATS * (int)sizeof(float));
    cudaFuncSetAttribute(dcn_mma_k, cudaFuncAttributeMaxDynamicSharedMemorySize,
                         DCN_FLOATS * (int)sizeof(float));

    transpose_wdcn_k<<<(GN*KKN*CG*CG + 255)/256, 256>>>(w_dcn);
    prep_wA_k<<<(8*KKN*OCP*32 + 255)/256, 256>>>(w_off);
    transpose_x_k<<<dim3(HWN/32, CG/32, BN*GN), dim3(32, 8)>>>(x);
    offset_conv_mma_k<<<dim3(HN/2, BN), 256, OFC_FLOATS * sizeof(float)>>>(x, b_off);
    dcn_mma_k<<<dim3(HN/4, GN, BN), 256, DCN_FLOATS * sizeof(float)>>>(b_dcn);
    ln_gate_k<<<dim3(HN*2, BN), 256>>>(x, gamma, beta, out);
}

// round 6
// speedup vs baseline: 1.4676x; 1.4676x over previous
#include <cuda_runtime.h>
#include <cstdint>

// Problem constants
#define BN   8
#define CN   256
#define HN   64
#define WN   64
#define GN   4
#define KKN  9
#define CG   64
#define OCF  108
#define OCP  128      // padded offset-conv out channels
#define HWN  (HN*WN)

// ---------------------------------------------------------------------------
// Scratch
// ---------------------------------------------------------------------------
__device__ float g_off[BN*OCF*HWN];          // offset/mask conv output
__device__ float g_out[BN*CN*HWN];           // DCN conv output (pre-LN)
__device__ float g_wT [GN*KKN*CG*CG];        // w_dcn as [g][k][oc][c], tf32-rounded
__device__ float g_wA [8*KKN*OCP*32];        // w_off as [cc][kk][oc 128][c 32], tf32-rounded
__device__ float g_xQ [BN*GN*16*HWN*4];      // x 4-ch interleave: [b][g][c4][px][4]

// ---------------------------------------------------------------------------
// helpers
// ---------------------------------------------------------------------------
__device__ __forceinline__ float tf32r(float v) {
    uint32_t u; asm("cvt.rna.tf32.f32 %0, %1;" : "=r"(u) : "f"(v));
    return __uint_as_float(u);
}
__device__ __forceinline__ void mma_tf32(float* d, const uint32_t* a,
                                         uint32_t b0, uint32_t b1) {
    asm volatile(
        "mma.sync.aligned.m16n8k8.row.col.f32.tf32.tf32.f32 "
        "{%0,%1,%2,%3}, {%4,%5,%6,%7}, {%8,%9}, {%0,%1,%2,%3};"
        : "+f"(d[0]), "+f"(d[1]), "+f"(d[2]), "+f"(d[3])
        : "r"(a[0]), "r"(a[1]), "r"(a[2]), "r"(a[3]), "r"(b0), "r"(b1));
}

// ---------------------------------------------------------------------------
// Kernel 0a: w_dcn [256][64][3][3] -> g_wT[g][k][oc][c] (tf32-rounded)
// ---------------------------------------------------------------------------
__global__ void __launch_bounds__(256) transpose_wdcn_k(const float* __restrict__ w_dcn)
{
    int i = blockIdx.x * 256 + threadIdx.x;
    if (i < GN*KKN*CG*CG) {
        int c  = i & 63;
        int oc = (i >> 6) & 63;
        int gk = i >> 12;
        int k  = gk % 9;
        int g  = gk / 9;
        g_wT[i] = tf32r(w_dcn[((g*CG + oc)*CG + c)*KKN + k]);
    }
}

// ---------------------------------------------------------------------------
// Kernel 0b: w_off -> g_wA[cc][kk][oc(128 pad)][c 32] (tf32-rounded)
// ---------------------------------------------------------------------------
__global__ void __launch_bounds__(256) prep_wA_k(const float* __restrict__ w_off)
{
    int i = blockIdx.x * 256 + threadIdx.x;
    if (i >= 8*KKN*OCP*32) return;
    int tile = i >> 12;
    int r    = i & 4095;
    int oc   = r >> 5;
    int c    = r & 31;
    int kk   = tile % 9;
    int cc   = tile / 9;
    float w = 0.f;
    if (oc < OCF) w = tf32r(w_off[(oc*CN + cc*32 + c)*KKN + kk]);
    g_wA[i] = w;
}

// ---------------------------------------------------------------------------
// Kernel 0c: build g_xQ[b][g][c4][px][4] from x [b][c][px].
// grid (HWN/256, 16, BN*GN), block 256. Thread: one (c4, px) -> float4.
// Reads 4 coalesced channel rows, writes one coalesced float4 row.
// ---------------------------------------------------------------------------
__global__ void __launch_bounds__(256) build_xQ_k(const float* __restrict__ x)
{
    const int bg = blockIdx.z;
    const int c4 = blockIdx.y;
    const int px = blockIdx.x * 256 + threadIdx.x;
    const float* src = x + (size_t)bg*CG*HWN + c4*4*HWN + px;
    float4 v;
    v.x = src[0];
    v.y = src[HWN];
    v.z = src[2*HWN];
    v.w = src[3*HWN];
    *reinterpret_cast<float4*>(g_xQ + ((size_t)(bg*16 + c4)*HWN + px)*4) = v;
}

// ---------------------------------------------------------------------------
// Kernel 1: offset/mask conv via mma.sync tf32 (exact round-4 version).
// grid (HN/2, BN), block 256 (8 warps). Block: 2 rows x 64 px x 128 oc(pad).
// smem (floats): patch [32c][4r][66] pitch264 @0 (8448); Wt [128oc][36] @8448
// ---------------------------------------------------------------------------
#define OFC_WT     8448
#define OFC_FLOATS (OFC_WT + OCP*36)

__global__ void __launch_bounds__(256, 2) offset_conv_mma_k(
    const float* __restrict__ x, const float* __restrict__ b_off)
{
    extern __shared__ float sm[];
    float* patch = sm;
    float* Wt    = sm + OFC_WT;
    const uint32_t* PU  = (const uint32_t*)patch;
    const uint32_t* WtU = (const uint32_t*)Wt;

    const int h0  = blockIdx.x * 2;
    const int b   = blockIdx.y;
    const int t   = threadIdx.x;
    const int wid = t >> 5;
    const int lane = t & 31;
    const int lm4 = lane & 3;
    const int ld4 = lane >> 2;
    const int mg  = wid & 3;
    const int ng  = wid >> 2;

    float D[2][8][4];
#pragma unroll
    for (int s = 0; s < 2; s++)
#pragma unroll
        for (int n = 0; n < 8; n++)
#pragma unroll
            for (int i = 0; i < 4; i++) D[s][n][i] = 0.f;

    for (int cc = 0; cc < 8; cc++) {
        __syncthreads();
        for (int i = t; i < 32*4*66; i += 256) {
            int c   = i / 264;
            int rem = i - c*264;
            int r   = rem / 66;
            int col = rem - r*66;
            int y   = h0 - 1 + r;
            int xx  = col - 1;
            float v = 0.f;
            if (y >= 0 && y < HN && xx >= 0 && xx < WN)
                v = x[((b*CN + cc*32 + c)*HN + y)*WN + xx];
            patch[c*264 + r*66 + col] = tf32r(v);
        }
        for (int kk = 0; kk < KKN; kk++) {
            __syncthreads();
            {
                const float4* src = (const float4*)(g_wA + (cc*9 + kk)*4096);
                for (int i = t; i < 1024; i += 256) {
                    float4 v = src[i];
                    int oc = i >> 3, c4 = (i & 7) * 4;
                    *reinterpret_cast<float4*>(&Wt[oc*36 + c4]) = v;
                }
            }
            __syncthreads();

            const int ky = kk / 3, kx = kk - (kk/3)*3;
            const int rbase = (ng + ky)*66 + kx + ld4;
#pragma unroll
            for (int step = 0; step < 4; step++) {
                const int k0 = step*8;
                uint32_t a[2][4];
#pragma unroll
                for (int s = 0; s < 2; s++) {
                    int ro = (mg*32 + s*16 + ld4)*36 + k0 + lm4;
                    a[s][0] = WtU[ro];
                    a[s][1] = WtU[ro + 8*36];
                    a[s][2] = WtU[ro + 4];
                    a[s][3] = WtU[ro + 8*36 + 4];
                }
                const int bb = (k0 + lm4)*264 + rbase;
#pragma unroll
                for (int nt = 0; nt < 8; nt++) {
                    uint32_t b0 = PU[bb + nt*8];
                    uint32_t b1 = PU[bb + nt*8 + 4*264];
                    mma_tf32(D[0][nt], a[0], b0, b1);
                    mma_tf32(D[1][nt], a[1], b0, b1);
                }
            }
        }
    }

    const int h = h0 + ng;
#pragma unroll
    for (int s = 0; s < 2; s++) {
#pragma unroll
        for (int nt = 0; nt < 8; nt++) {
            int ocA = mg*32 + s*16 + ld4;
            int ocB = ocA + 8;
            int w   = nt*8 + lm4*2;
            if (ocA < OCF) {
                float bo = b_off[ocA];
                *reinterpret_cast<float2*>(&g_off[((b*OCF + ocA)*HN + h)*WN + w])
                    = make_float2(D[s][nt][0] + bo, D[s][nt][1] + bo);
            }
            if (ocB < OCF) {
                float bo = b_off[ocB];
                *reinterpret_cast<float2*>(&g_off[((b*OCF + ocB)*HN + h)*WN + w])
                    = make_float2(D[s][nt][2] + bo, D[s][nt][3] + bo);
            }
        }
    }
}

// ---------------------------------------------------------------------------
// Kernel 2: deformable sampling + grouped conv (round-4 layout, gather via
// g_xQ float4 4-channel interleave — lane-coalesced LDG.128).
// grid (HN/4, GN, BN), block 256 (8 warps). Block: 4 rows x 64 px x 64 oc.
// smem (floats): Wsm [64oc][68] @0 (4352); S [64c][264] @4352 (16896)
// ---------------------------------------------------------------------------
#define DCN_S      4352
#define DCN_FLOATS (DCN_S + CG*264)

__global__ void __launch_bounds__(256, 2) dcn_mma_k(
    const float* __restrict__ b_dcn)
{
    extern __shared__ float sm[];
    float* Wsm = sm;
    float* S   = sm + DCN_S;
    const uint32_t* WU = (const uint32_t*)Wsm;
    const uint32_t* SU = (const uint32_t*)S;

    const int h0 = blockIdx.x * 4;
    const int g  = blockIdx.y;
    const int b  = blockIdx.z;
    const int t  = threadIdx.x;
    const int wid = t >> 5;
    const int lane = t & 31;
    const int lm4 = lane & 3;
    const int ld4 = lane >> 2;
    const int mg  = wid & 1;          // oc base mg*32
    const int ng  = wid >> 1;         // px row (0..3)

    const int pxA = t;                // pixel owned by this thread
    const int hA  = h0 + (t >> 6);
    const int wA  = t & 63;
    const float* xq = g_xQ + (size_t)(b*GN + g)*16*HWN*4;

    float D[2][8][4];
#pragma unroll
    for (int s = 0; s < 2; s++)
#pragma unroll
        for (int n = 0; n < 8; n++)
#pragma unroll
            for (int i = 0; i < 4; i++) D[s][n][i] = 0.f;

    for (int k = 0; k < KKN; k++) {
        __syncthreads();   // previous mma done reading S/Wsm
        // ---- bilinear corner data (registers) ----
        int i0, i1, i2, i3; float w0, w1, w2, w3;
        {
            int ky = k / 3 - 1;
            int kx = k - (k/3)*3 - 1;
            int sp = hA*WN + wA;
            const float* ob = g_off + b*OCF*HWN;
            float oy = ob[((g*KKN + k)*2    )*HWN + sp];
            float ox = ob[((g*KKN + k)*2 + 1)*HWN + sp];
            float mz = ob[(2*GN*KKN + g*KKN + k)*HWN + sp];
            float mk = 1.f / (1.f + expf(-mz));
            float py  = (float)(hA + ky) + oy;
            float pxx = (float)(wA + kx) + ox;
            float y0f = floorf(py),  x0f = floorf(pxx);
            float wy1 = py - y0f,    wx1 = pxx - x0f;
            float wy0 = 1.f - wy1,   wx0 = 1.f - wx1;
            int y0 = (int)y0f, x0i = (int)x0f;
            int y1 = y0 + 1,   x1i = x0i + 1;
            bool vy0 = (y0 >= 0) & (y0 < HN);
            bool vy1 = (y1 >= 0) & (y1 < HN);
            bool vx0 = (x0i >= 0) & (x0i < WN);
            bool vx1 = (x1i >= 0) & (x1i < WN);
            int y0c = min(max(y0, 0), HN-1), y1c = min(max(y1, 0), HN-1);
            int x0c = min(max(x0i,0), WN-1), x1c = min(max(x1i,0), WN-1);
            i0 = y0c*WN + x0c;  i1 = y0c*WN + x1c;
            i2 = y1c*WN + x0c;  i3 = y1c*WN + x1c;
            w0 = (vy0 && vx0) ? wy0*wx0*mk : 0.f;
            w1 = (vy0 && vx1) ? wy0*wx1*mk : 0.f;
            w2 = (vy1 && vx0) ? wy1*wx0*mk : 0.f;
            w3 = (vy1 && vx1) ? wy1*wx1*mk : 0.f;
        }
        // ---- stage weight tile [64 oc][64 c] -> Wsm[oc*68 + c] ----
        {
            const float* wt = g_wT + (g*KKN + k)*CG*CG;
            for (int i = t; i < CG*CG; i += 256)
                Wsm[(i >> 6)*68 + (i & 63)] = wt[i];
        }
        // ---- gather: 16 c4-chunks, 4 corner LDG.128 each (lane-coalesced) ----
#pragma unroll 4
        for (int c4 = 0; c4 < 16; c4++) {
            const float4* plane = (const float4*)(xq + (size_t)c4*HWN*4);
            float4 A = plane[i0], Bv = plane[i1], Cv = plane[i2], Dv = plane[i3];
            float* sc = S + (c4*4)*264 + pxA;
            sc[0]     = tf32r(w0*A.x + w1*Bv.x + w2*Cv.x + w3*Dv.x);
            sc[264]   = tf32r(w0*A.y + w1*Bv.y + w2*Cv.y + w3*Dv.y);
            sc[2*264] = tf32r(w0*A.z + w1*Bv.z + w2*Cv.z + w3*Dv.z);
            sc[3*264] = tf32r(w0*A.w + w1*Bv.w + w2*Cv.w + w3*Dv.w);
        }
        __syncthreads();

        // ---- mma: K=64 -> 8 k8-steps ----
#pragma unroll
        for (int step = 0; step < 8; step++) {
            const int k0 = step*8;
            uint32_t a[2][4];
#pragma unroll
            for (int s = 0; s < 2; s++) {
                int ro = (mg*32 + s*16 + ld4)*68 + k0 + lm4;
                a[s][0] = WU[ro];
                a[s][1] = WU[ro + 8*68];
                a[s][2] = WU[ro + 4];
                a[s][3] = WU[ro + 8*68 + 4];
            }
            const int bb = (k0 + lm4)*264 + ng*64 + ld4;
#pragma unroll
            for (int nt = 0; nt < 8; nt++) {
                uint32_t b0 = SU[bb + nt*8];
                uint32_t b1 = SU[bb + nt*8 + 4*264];
                mma_tf32(D[0][nt], a[0], b0, b1);
                mma_tf32(D[1][nt], a[1], b0, b1);
            }
        }
    }

    // ---- epilogue: +bias, store ----
    const int h = h0 + ng;
#pragma unroll
    for (int s = 0; s < 2; s++) {
#pragma unroll
        for (int nt = 0; nt < 8; nt++) {
            int ocA = g*CG + mg*32 + s*16 + ld4;
            int ocB = ocA + 8;
            int w   = nt*8 + lm4*2;
            float boA = b_dcn[ocA], boB = b_dcn[ocB];
            *reinterpret_cast<float2*>(&g_out[((b*CN + ocA)*HN + h)*WN + w])
                = make_float2(D[s][nt][0] + boA, D[s][nt][1] + boA);
            *reinterpret_cast<float2*>(&g_out[((b*CN + ocB)*HN + h)*WN + w])
                = make_float2(D[s][nt][2] + boB, D[s][nt][3] + boB);
        }
    }
}

// ---------------------------------------------------------------------------
// Kernel 3: LayerNorm over C + sigmoid + gate
// ---------------------------------------------------------------------------
__global__ void __launch_bounds__(256) ln_gate_k(
    const float* __restrict__ x, const float* __restrict__ gamma,
    const float* __restrict__ beta, float* __restrict__ out)
{
    __shared__ float tile[CN][32];
    __shared__ float rs[8][32];
    __shared__ float rq[8][32];
    __shared__ float smu[32], srinv[32];

    const int b    = blockIdx.y;
    const int h    = blockIdx.x >> 1;
    const int wseg = (blockIdx.x & 1) * 32;
    const int t    = threadIdx.x;
    const int base = b*CN*HWN + h*WN + wseg;

    for (int i = t; i < CN*32; i += 256) {
        int c = i >> 5, p = i & 31;
        tile[c][p] = g_out[base + c*HWN + p];
    }
    __syncthreads();
    {
        int p = t & 31, part = t >> 5;
        float s = 0.f, q = 0.f;
        for (int c = part; c < CN; c += 8) {
            float v = tile[c][p];
            s += v; q += v*v;
        }
        rs[part][p] = s; rq[part][p] = q;
    }
    __syncthreads();
    if (t < 32) {
        float s = 0.f, q = 0.f;
#pragma unroll
        for (int part = 0; part < 8; part++) { s += rs[part][t]; q += rq[part][t]; }
        float mu  = s * (1.f/CN);
        float var = fmaxf(q * (1.f/CN) - mu*mu, 0.f);
        smu[t]   = mu;
        srinv[t] = rsqrtf(var + 1e-5f);
    }
    __syncthreads();
    for (int i = t; i < CN*32; i += 256) {
        int c = i >> 5, p = i & 31;
        float z = (tile[c][p] - smu[p]) * srinv[p] * gamma[c] + beta[c];
        float a = 1.f / (1.f + expf(-z));
        int idx = base + c*HWN + p;
        out[idx] = x[idx] * a;
    }
}

// ---------------------------------------------------------------------------
// Entry point
// ---------------------------------------------------------------------------
extern "C" void kernel_launch(void* const* d_in, const int* in_sizes, int n_in,
                              void* d_out, int out_size)
{
    const float* x     = (const float*)d_in[0];
    const float* w_off = (const float*)d_in[1];
    const float* b_off = (const float*)d_in[2];
    const float* w_dcn = (const float*)d_in[3];
    const float* b_dcn = (const float*)d_in[4];
    const float* gamma = (const float*)d_in[5];
    const float* beta  = (const float*)d_in[6];
    float* out = (float*)d_out;

    (void)in_sizes; (void)n_in; (void)out_size;

    cudaFuncSetAttribute(offset_conv_mma_k, cudaFuncAttributeMaxDynamicSharedMemorySize,
                         OFC_FLOATS * (int)sizeof(float));
    cudaFuncSetAttribute(dcn_mma_k, cudaFuncAttributeMaxDynamicSharedMemorySize,
                         DCN_FLOATS * (int)sizeof(float));

    transpose_wdcn_k<<<(GN*KKN*CG*CG + 255)/256, 256>>>(w_dcn);
    prep_wA_k<<<(8*KKN*OCP*32 + 255)/256, 256>>>(w_off);
    build_xQ_k<<<dim3(HWN/256, 16, BN*GN), 256>>>(x);
    offset_conv_mma_k<<<dim3(HN/2, BN), 256, OFC_FLOATS * sizeof(float)>>>(x, b_off);
    dcn_mma_k<<<dim3(HN/4, GN, BN), 256, DCN_FLOATS * sizeof(float)>>>(b_dcn);
    ln_gate_k<<<dim3(HN*2, BN), 256>>>(x, gamma, beta, out);
}

// round 7
// speedup vs baseline: 1.5683x; 1.0686x over previous
#include <cuda_runtime.h>
#include <cstdint>

// Problem constants
#define BN   8
#define CN   256
#define HN   64
#define WN   64
#define GN   4
#define KKN  9
#define CG   64
#define OCF  108
#define OCP  128      // padded offset-conv out channels
#define HWN  (HN*WN)

// ---------------------------------------------------------------------------
// Scratch
// ---------------------------------------------------------------------------
__device__ float g_off[BN*OCF*HWN];          // offset/mask conv output
__device__ float g_out[BN*CN*HWN];           // DCN conv output (pre-LN)
__device__ float g_wT [GN*KKN*CG*CG];        // w_dcn as [g][k][oc][c], tf32-rounded
__device__ float g_wA [8*KKN*OCP*32];        // w_off as [cc][kk][oc 128][c 32], tf32-rounded
__device__ float g_xQ [BN*GN*16*HWN*4];      // x 4-ch interleave: [b][g][c4][px][4]

// ---------------------------------------------------------------------------
// helpers
// ---------------------------------------------------------------------------
__device__ __forceinline__ float tf32r(float v) {
    uint32_t u; asm("cvt.rna.tf32.f32 %0, %1;" : "=r"(u) : "f"(v));
    return __uint_as_float(u);
}
__device__ __forceinline__ void mma_tf32(float* d, const uint32_t* a,
                                         uint32_t b0, uint32_t b1) {
    asm volatile(
        "mma.sync.aligned.m16n8k8.row.col.f32.tf32.tf32.f32 "
        "{%0,%1,%2,%3}, {%4,%5,%6,%7}, {%8,%9}, {%0,%1,%2,%3};"
        : "+f"(d[0]), "+f"(d[1]), "+f"(d[2]), "+f"(d[3])
        : "r"(a[0]), "r"(a[1]), "r"(a[2]), "r"(a[3]), "r"(b0), "r"(b1));
}
__device__ __forceinline__ uint32_t smem_u32(const void* p) {
    uint32_t a;
    asm("{ .reg .u64 t; cvta.to.shared.u64 t, %1; cvt.u32.u64 %0, t; }" : "=r"(a) : "l"(p));
    return a;
}
#define CP_ASYNC16(dst, src) \
    asm volatile("cp.async.cg.shared.global [%0], [%1], 16;" :: "r"(dst), "l"(src))
#define CP_COMMIT() asm volatile("cp.async.commit_group;" ::: "memory")
#define CP_WAIT0()  asm volatile("cp.async.wait_group 0;" ::: "memory")

// ---------------------------------------------------------------------------
// Kernel 0a: w_dcn [256][64][3][3] -> g_wT[g][k][oc][c] (tf32-rounded)
// ---------------------------------------------------------------------------
__global__ void __launch_bounds__(256) transpose_wdcn_k(const float* __restrict__ w_dcn)
{
    int i = blockIdx.x * 256 + threadIdx.x;
    if (i < GN*KKN*CG*CG) {
        int c  = i & 63;
        int oc = (i >> 6) & 63;
        int gk = i >> 12;
        int k  = gk % 9;
        int g  = gk / 9;
        g_wT[i] = tf32r(w_dcn[((g*CG + oc)*CG + c)*KKN + k]);
    }
}

// ---------------------------------------------------------------------------
// Kernel 0b: w_off -> g_wA[cc][kk][oc(128 pad)][c 32] (tf32-rounded)
// ---------------------------------------------------------------------------
__global__ void __launch_bounds__(256) prep_wA_k(const float* __restrict__ w_off)
{
    int i = blockIdx.x * 256 + threadIdx.x;
    if (i >= 8*KKN*OCP*32) return;
    int tile = i >> 12;
    int r    = i & 4095;
    int oc   = r >> 5;
    int c    = r & 31;
    int kk   = tile % 9;
    int cc   = tile / 9;
    float w = 0.f;
    if (oc < OCF) w = tf32r(w_off[(oc*CN + cc*32 + c)*KKN + kk]);
    g_wA[i] = w;
}

// ---------------------------------------------------------------------------
// Kernel 0c: build g_xQ[b][g][c4][px][4] from x [b][c][px].
// ---------------------------------------------------------------------------
__global__ void __launch_bounds__(256) build_xQ_k(const float* __restrict__ x)
{
    const int bg = blockIdx.z;
    const int c4 = blockIdx.y;
    const int px = blockIdx.x * 256 + threadIdx.x;
    const float* src = x + (size_t)bg*CG*HWN + c4*4*HWN + px;
    float4 v;
    v.x = src[0];
    v.y = src[HWN];
    v.z = src[2*HWN];
    v.w = src[3*HWN];
    *reinterpret_cast<float4*>(g_xQ + ((size_t)(bg*16 + c4)*HWN + px)*4) = v;
}

// ---------------------------------------------------------------------------
// Kernel 1: offset/mask conv via mma.sync tf32, cp.async double-buffered W.
// grid (HN/2, BN), block 256 (8 warps). Block: 2 rows x 64 px x 128 oc(pad).
// smem (floats): patch [32c][4r][66] pitch264 @0 (8448); Wt[2][128oc][36] @8448
// ---------------------------------------------------------------------------
#define OFC_WT     8448
#define OFC_FLOATS (OFC_WT + 2*OCP*36)

__device__ __forceinline__ void ofc_prefetch_wt(float* Wb, int tile, int t)
{
    uint32_t base = smem_u32(Wb);
    const float* src = g_wA + tile*4096;
#pragma unroll
    for (int j = 0; j < 4; j++) {
        int i  = t + j*256;
        int oc = i >> 3, c4 = (i & 7)*4;
        CP_ASYNC16(base + (oc*36 + c4)*4, src + i*4);
    }
}

__global__ void __launch_bounds__(256, 2) offset_conv_mma_k(
    const float* __restrict__ x, const float* __restrict__ b_off)
{
    extern __shared__ float sm[];
    float* patch = sm;
    const uint32_t* PU = (const uint32_t*)patch;

    const int h0  = blockIdx.x * 2;
    const int b   = blockIdx.y;
    const int t   = threadIdx.x;
    const int wid = t >> 5;
    const int lane = t & 31;
    const int lm4 = lane & 3;
    const int ld4 = lane >> 2;
    const int mg  = wid & 3;
    const int ng  = wid >> 2;

    float D[2][8][4];
#pragma unroll
    for (int s = 0; s < 2; s++)
#pragma unroll
        for (int n = 0; n < 8; n++)
#pragma unroll
            for (int i = 0; i < 4; i++) D[s][n][i] = 0.f;

    // prologue: prefetch weight tile 0
    ofc_prefetch_wt(sm + OFC_WT, 0, t);
    CP_COMMIT();

    for (int idx = 0; idx < 72; idx++) {
        const int cc = idx / 9, kk = idx - cc*9;

        CP_WAIT0();           // current tile resident
        __syncthreads();      // all warps past previous mma (buffers + patch free)
        if (idx < 71)
            ofc_prefetch_wt(sm + OFC_WT + ((idx+1) & 1)*OCP*36, idx+1, t);
        CP_COMMIT();

        if (kk == 0) {
            // load patch: 32 ch x 4 rows (h0-1..h0+2) x 66 cols
            for (int i = t; i < 32*4*66; i += 256) {
                int c   = i / 264;
                int rem = i - c*264;
                int r   = rem / 66;
                int col = rem - r*66;
                int y   = h0 - 1 + r;
                int xx  = col - 1;
                float v = 0.f;
                if (y >= 0 && y < HN && xx >= 0 && xx < WN)
                    v = x[((b*CN + cc*32 + c)*HN + y)*WN + xx];
                patch[c*264 + r*66 + col] = tf32r(v);
            }
            __syncthreads();
        }

        const uint32_t* WtU = (const uint32_t*)(sm + OFC_WT + (idx & 1)*OCP*36);
        const int ky = kk / 3, kx = kk - (kk/3)*3;
        const int rbase = (ng + ky)*66 + kx + ld4;
#pragma unroll
        for (int step = 0; step < 4; step++) {
            const int k0 = step*8;
            uint32_t a[2][4];
#pragma unroll
            for (int s = 0; s < 2; s++) {
                int ro = (mg*32 + s*16 + ld4)*36 + k0 + lm4;
                a[s][0] = WtU[ro];
                a[s][1] = WtU[ro + 8*36];
                a[s][2] = WtU[ro + 4];
                a[s][3] = WtU[ro + 8*36 + 4];
            }
            const int bb = (k0 + lm4)*264 + rbase;
#pragma unroll
            for (int nt = 0; nt < 8; nt++) {
                uint32_t b0 = PU[bb + nt*8];
                uint32_t b1 = PU[bb + nt*8 + 4*264];
                mma_tf32(D[0][nt], a[0], b0, b1);
                mma_tf32(D[1][nt], a[1], b0, b1);
            }
        }
    }

    const int h = h0 + ng;
#pragma unroll
    for (int s = 0; s < 2; s++) {
#pragma unroll
        for (int nt = 0; nt < 8; nt++) {
            int ocA = mg*32 + s*16 + ld4;
            int ocB = ocA + 8;
            int w   = nt*8 + lm4*2;
            if (ocA < OCF) {
                float bo = b_off[ocA];
                *reinterpret_cast<float2*>(&g_off[((b*OCF + ocA)*HN + h)*WN + w])
                    = make_float2(D[s][nt][0] + bo, D[s][nt][1] + bo);
            }
            if (ocB < OCF) {
                float bo = b_off[ocB];
                *reinterpret_cast<float2*>(&g_off[((b*OCF + ocB)*HN + h)*WN + w])
                    = make_float2(D[s][nt][2] + bo, D[s][nt][3] + bo);
            }
        }
    }
}

// ---------------------------------------------------------------------------
// Kernel 2: deformable sampling + grouped conv, xQ gather + cp.async W tiles.
// grid (HN/4, GN, BN), block 256 (8 warps). Block: 4 rows x 64 px x 64 oc.
// smem (floats): Wsm[2][64oc][68] @0 (8704); S [64c][264] @8704 (16896)
// ---------------------------------------------------------------------------
#define DCN_S      8704
#define DCN_FLOATS (DCN_S + CG*264)

__device__ __forceinline__ void dcn_prefetch_w(float* Wb, int tile, int t)
{
    uint32_t base = smem_u32(Wb);
    const float* src = g_wT + tile*4096;
#pragma unroll
    for (int j = 0; j < 4; j++) {
        int i  = t + j*256;
        int oc = i >> 4, c4 = (i & 15)*4;
        CP_ASYNC16(base + (oc*68 + c4)*4, src + i*4);
    }
}

__global__ void __launch_bounds__(256, 2) dcn_mma_k(
    const float* __restrict__ b_dcn)
{
    extern __shared__ float sm[];
    float* S = sm + DCN_S;
    const uint32_t* SU = (const uint32_t*)S;

    const int h0 = blockIdx.x * 4;
    const int g  = blockIdx.y;
    const int b  = blockIdx.z;
    const int t  = threadIdx.x;
    const int wid = t >> 5;
    const int lane = t & 31;
    const int lm4 = lane & 3;
    const int ld4 = lane >> 2;
    const int mg  = wid & 1;          // oc base mg*32
    const int ng  = wid >> 1;         // px row (0..3)

    const int pxA = t;                // pixel owned by this thread
    const int hA  = h0 + (t >> 6);
    const int wA  = t & 63;
    const float* xq = g_xQ + (size_t)(b*GN + g)*16*HWN*4;

    float D[2][8][4];
#pragma unroll
    for (int s = 0; s < 2; s++)
#pragma unroll
        for (int n = 0; n < 8; n++)
#pragma unroll
            for (int i = 0; i < 4; i++) D[s][n][i] = 0.f;

    // prologue: prefetch weight tile k=0
    dcn_prefetch_w(sm, (g*KKN + 0), t);
    CP_COMMIT();

    for (int k = 0; k < KKN; k++) {
        CP_WAIT0();
        __syncthreads();   // previous mma done reading S/W buffers
        if (k < KKN-1)
            dcn_prefetch_w(sm + ((k+1) & 1)*CG*68, g*KKN + k + 1, t);
        CP_COMMIT();

        // ---- bilinear corner data (registers) ----
        int i0, i1, i2, i3; float w0, w1, w2, w3;
        {
            int ky = k / 3 - 1;
            int kx = k - (k/3)*3 - 1;
            int sp = hA*WN + wA;
            const float* ob = g_off + b*OCF*HWN;
            float oy = ob[((g*KKN + k)*2    )*HWN + sp];
            float ox = ob[((g*KKN + k)*2 + 1)*HWN + sp];
            float mz = ob[(2*GN*KKN + g*KKN + k)*HWN + sp];
            float mk = 1.f / (1.f + expf(-mz));
            float py  = (float)(hA + ky) + oy;
            float pxx = (float)(wA + kx) + ox;
            float y0f = floorf(py),  x0f = floorf(pxx);
            float wy1 = py - y0f,    wx1 = pxx - x0f;
            float wy0 = 1.f - wy1,   wx0 = 1.f - wx1;
            int y0 = (int)y0f, x0i = (int)x0f;
            int y1 = y0 + 1,   x1i = x0i + 1;
            bool vy0 = (y0 >= 0) & (y0 < HN);
            bool vy1 = (y1 >= 0) & (y1 < HN);
            bool vx0 = (x0i >= 0) & (x0i < WN);
            bool vx1 = (x1i >= 0) & (x1i < WN);
            int y0c = min(max(y0, 0), HN-1), y1c = min(max(y1, 0), HN-1);
            int x0c = min(max(x0i,0), WN-1), x1c = min(max(x1i,0), WN-1);
            i0 = y0c*WN + x0c;  i1 = y0c*WN + x1c;
            i2 = y1c*WN + x0c;  i3 = y1c*WN + x1c;
            w0 = (vy0 && vx0) ? wy0*wx0*mk : 0.f;
            w1 = (vy0 && vx1) ? wy0*wx1*mk : 0.f;
            w2 = (vy1 && vx0) ? wy1*wx0*mk : 0.f;
            w3 = (vy1 && vx1) ? wy1*wx1*mk : 0.f;
        }
        // ---- gather: 16 c4-chunks, 4 corner LDG.128 each (lane-coalesced) ----
#pragma unroll 4
        for (int c4 = 0; c4 < 16; c4++) {
            const float4* plane = (const float4*)(xq + (size_t)c4*HWN*4);
            float4 A = plane[i0], Bv = plane[i1], Cv = plane[i2], Dv = plane[i3];
            float* sc = S + (c4*4)*264 + pxA;
            sc[0]     = tf32r(w0*A.x + w1*Bv.x + w2*Cv.x + w3*Dv.x);
            sc[264]   = tf32r(w0*A.y + w1*Bv.y + w2*Cv.y + w3*Dv.y);
            sc[2*264] = tf32r(w0*A.z + w1*Bv.z + w2*Cv.z + w3*Dv.z);
            sc[3*264] = tf32r(w0*A.w + w1*Bv.w + w2*Cv.w + w3*Dv.w);
        }
        __syncthreads();

        // ---- mma: K=64 -> 8 k8-steps ----
        const uint32_t* WU = (const uint32_t*)(sm + (k & 1)*CG*68);
#pragma unroll
        for (int step = 0; step < 8; step++) {
            const int k0 = step*8;
            uint32_t a[2][4];
#pragma unroll
            for (int s = 0; s < 2; s++) {
                int ro = (mg*32 + s*16 + ld4)*68 + k0 + lm4;
                a[s][0] = WU[ro];
                a[s][1] = WU[ro + 8*68];
                a[s][2] = WU[ro + 4];
                a[s][3] = WU[ro + 8*68 + 4];
            }
            const int bb = (k0 + lm4)*264 + ng*64 + ld4;
#pragma unroll
            for (int nt = 0; nt < 8; nt++) {
                uint32_t b0 = SU[bb + nt*8];
                uint32_t b1 = SU[bb + nt*8 + 4*264];
                mma_tf32(D[0][nt], a[0], b0, b1);
                mma_tf32(D[1][nt], a[1], b0, b1);
            }
        }
    }

    // ---- epilogue: +bias, store ----
    const int h = h0 + ng;
#pragma unroll
    for (int s = 0; s < 2; s++) {
#pragma unroll
        for (int nt = 0; nt < 8; nt++) {
            int ocA = g*CG + mg*32 + s*16 + ld4;
            int ocB = ocA + 8;
            int w   = nt*8 + lm4*2;
            float boA = b_dcn[ocA], boB = b_dcn[ocB];
            *reinterpret_cast<float2*>(&g_out[((b*CN + ocA)*HN + h)*WN + w])
                = make_float2(D[s][nt][0] + boA, D[s][nt][1] + boA);
            *reinterpret_cast<float2*>(&g_out[((b*CN + ocB)*HN + h)*WN + w])
                = make_float2(D[s][nt][2] + boB, D[s][nt][3] + boB);
        }
    }
}

// ---------------------------------------------------------------------------
// Kernel 3: LayerNorm over C + sigmoid + gate — register-resident values.
// grid (HN*2, BN), block 256. Thread: 32 channels of one pixel.
// ---------------------------------------------------------------------------
__global__ void __launch_bounds__(256) ln_gate_k(
    const float* __restrict__ x, const float* __restrict__ gamma,
    const float* __restrict__ beta, float* __restrict__ out)
{
    __shared__ float rs[8][32];
    __shared__ float rq[8][32];
    __shared__ float smu[32], srinv[32];

    const int b    = blockIdx.y;
    const int h    = blockIdx.x >> 1;
    const int wseg = (blockIdx.x & 1) * 32;
    const int t    = threadIdx.x;
    const int gi   = t >> 5;
    const int lane = t & 31;
    const int base = b*CN*HWN + h*WN + wseg + lane;

    const float* src = g_out + base + gi*32*HWN;
    float v[32];
    float s = 0.f, q = 0.f;
#pragma unroll
    for (int cc = 0; cc < 32; cc++) {
        float vv = src[cc*HWN];
        v[cc] = vv;
        s += vv; q += vv*vv;
    }
    rs[gi][lane] = s; rq[gi][lane] = q;
    __syncthreads();
    if (t < 32) {
        float ss = 0.f, qq = 0.f;
#pragma unroll
        for (int part = 0; part < 8; part++) { ss += rs[part][t]; qq += rq[part][t]; }
        float mu  = ss * (1.f/CN);
        float var = fmaxf(qq * (1.f/CN) - mu*mu, 0.f);
        smu[t]   = mu;
        srinv[t] = rsqrtf(var + 1e-5f);
    }
    __syncthreads();
    const float mu   = smu[lane];
    const float rinv = srinv[lane];
    const float* xp  = x + base + gi*32*HWN;
    float* op        = out + base + gi*32*HWN;
#pragma unroll
    for (int cc = 0; cc < 32; cc++) {
        int c = gi*32 + cc;
        float z = (v[cc] - mu) * rinv * gamma[c] + beta[c];
        float a = 1.f / (1.f + expf(-z));
        op[cc*HWN] = xp[cc*HWN] * a;
    }
}

// ---------------------------------------------------------------------------
// Entry point
// ---------------------------------------------------------------------------
extern "C" void kernel_launch(void* const* d_in, const int* in_sizes, int n_in,
                              void* d_out, int out_size)
{
    const float* x     = (const float*)d_in[0];
    const float* w_off = (const float*)d_in[1];
    const float* b_off = (const float*)d_in[2];
    const float* w_dcn = (const float*)d_in[3];
    const float* b_dcn = (const float*)d_in[4];
    const float* gamma = (const float*)d_in[5];
    const float* beta  = (const float*)d_in[6];
    float* out = (float*)d_out;

    (void)in_sizes; (void)n_in; (void)out_size;

    cudaFuncSetAttribute(offset_conv_mma_k, cudaFuncAttributeMaxDynamicSharedMemorySize,
                         OFC_FLOATS * (int)sizeof(float));
    cudaFuncSetAttribute(dcn_mma_k, cudaFuncAttributeMaxDynamicSharedMemorySize,
                         DCN_FLOATS * (int)sizeof(float));

    transpose_wdcn_k<<<(GN*KKN*CG*CG + 255)/256, 256>>>(w_dcn);
    prep_wA_k<<<(8*KKN*OCP*32 + 255)/256, 256>>>(w_off);
    build_xQ_k<<<dim3(HWN/256, 16, BN*GN), 256>>>(x);
    offset_conv_mma_k<<<dim3(HN/2, BN), 256, OFC_FLOATS * sizeof(float)>>>(x, b_off);
    dcn_mma_k<<<dim3(HN/4, GN, BN), 256, DCN_FLOATS * sizeof(float)>>>(b_dcn);
    ln_gate_k<<<dim3(HN*2, BN), 256>>>(x, gamma, beta, out);
}

// round 8
// speedup vs baseline: 1.6803x; 1.0714x over previous
#include <cuda_runtime.h>
#include <cstdint>

// Problem constants
#define BN   8
#define CN   256
#define HN   64
#define WN   64
#define GN   4
#define KKN  9
#define CG   64
#define OCF  108
#define OCP  128
#define HWN  (HN*WN)

// ---------------------------------------------------------------------------
// Scratch
// ---------------------------------------------------------------------------
__device__ float g_off[BN*OCF*HWN];          // offset/mask conv output
__device__ float g_out[BN*CN*HWN];           // DCN conv output (pre-LN)
__device__ float g_wT [GN*KKN*4096];         // w_dcn fragment-baked per tile
__device__ float g_wA [8*KKN*4096];          // w_off fragment-baked per tile
__device__ float g_xQ [BN*GN*16*HWN*4];      // x 4-ch interleave: [b][g][c4][px][4]

// ---------------------------------------------------------------------------
// helpers
// ---------------------------------------------------------------------------
__device__ __forceinline__ float tf32r(float v) {
    uint32_t u; asm("cvt.rna.tf32.f32 %0, %1;" : "=r"(u) : "f"(v));
    return __uint_as_float(u);
}
__device__ __forceinline__ void mma_tf32(float* d, uint32_t a0, uint32_t a1,
                                         uint32_t a2, uint32_t a3,
                                         uint32_t b0, uint32_t b1) {
    asm volatile(
        "mma.sync.aligned.m16n8k8.row.col.f32.tf32.tf32.f32 "
        "{%0,%1,%2,%3}, {%4,%5,%6,%7}, {%8,%9}, {%0,%1,%2,%3};"
        : "+f"(d[0]), "+f"(d[1]), "+f"(d[2]), "+f"(d[3])
        : "r"(a0), "r"(a1), "r"(a2), "r"(a3), "r"(b0), "r"(b1));
}

// ---------------------------------------------------------------------------
// Kernel 0a: w_dcn -> g_wT fragment-baked.
// tile = g*9+k (4096 floats): [(mt*8+step)*32 + lane][r], r=0..3:
//   oc = mt*16 + (r&1)*8 + (lane>>2),  c = step*8 + (lane&3) + (r>>1)*4
// ---------------------------------------------------------------------------
__global__ void __launch_bounds__(256) prep_wT_k(const float* __restrict__ w_dcn)
{
    int i = blockIdx.x * 256 + threadIdx.x;
    if (i >= GN*KKN*4096) return;
    int tile = i >> 12;
    int r    = i & 3;
    int lane = (i >> 2) & 31;
    int fs   = (i >> 7) & 31;         // mt*8 + step
    int mt   = fs >> 3, step = fs & 7;
    int k    = tile % 9;
    int g    = tile / 9;
    int oc   = mt*16 + ((r & 1) << 3) + (lane >> 2);
    int c    = step*8 + (lane & 3) + ((r >> 1) << 2);
    g_wT[i] = tf32r(w_dcn[((g*CG + oc)*CG + c)*KKN + k]);
}

// ---------------------------------------------------------------------------
// Kernel 0b: w_off -> g_wA fragment-baked.
// tile = cc*9+kk: [(mt*4+step)*32 + lane][r]:
//   oc = mt*16 + (r&1)*8 + (lane>>2), c_local = step*8 + (lane&3) + (r>>1)*4
// ---------------------------------------------------------------------------
__global__ void __launch_bounds__(256) prep_wA_k(const float* __restrict__ w_off)
{
    int i = blockIdx.x * 256 + threadIdx.x;
    if (i >= 8*KKN*4096) return;
    int tile = i >> 12;
    int r    = i & 3;
    int lane = (i >> 2) & 31;
    int fs   = (i >> 7) & 31;         // mt*4 + step
    int mt   = fs >> 2, step = fs & 3;
    int kk   = tile % 9;
    int cc   = tile / 9;
    int oc   = mt*16 + ((r & 1) << 3) + (lane >> 2);
    int c    = step*8 + (lane & 3) + ((r >> 1) << 2);
    float w = 0.f;
    if (oc < OCF) w = tf32r(w_off[(oc*CN + cc*32 + c)*KKN + kk]);
    g_wA[i] = w;
}

// ---------------------------------------------------------------------------
// Kernel 0c: build g_xQ[b][g][c4][px][4] from x [b][c][px].
// ---------------------------------------------------------------------------
__global__ void __launch_bounds__(256) build_xQ_k(const float* __restrict__ x)
{
    const int bg = blockIdx.z;
    const int c4 = blockIdx.y;
    const int px = blockIdx.x * 256 + threadIdx.x;
    const float* src = x + (size_t)bg*CG*HWN + c4*4*HWN + px;
    float4 v;
    v.x = src[0];
    v.y = src[HWN];
    v.z = src[2*HWN];
    v.w = src[3*HWN];
    *reinterpret_cast<float4*>(g_xQ + ((size_t)(bg*16 + c4)*HWN + px)*4) = v;
}

// ---------------------------------------------------------------------------
// Kernel 1: offset/mask conv; A fragments via LDG.128 from g_wA (L1-hot),
// B from smem patch. No weight staging, no barriers inside kk loop.
// grid (HN/2, BN), block 256. smem: patch [32c][4r][66] pitch264 (33.8KB)
// ---------------------------------------------------------------------------
#define OFC_FLOATS 8448

__global__ void __launch_bounds__(256, 2) offset_conv_mma_k(
    const float* __restrict__ x, const float* __restrict__ b_off)
{
    extern __shared__ float sm[];
    float* patch = sm;
    const uint32_t* PU = (const uint32_t*)patch;

    const int h0  = blockIdx.x * 2;
    const int b   = blockIdx.y;
    const int t   = threadIdx.x;
    const int wid = t >> 5;
    const int lane = t & 31;
    const int lm4 = lane & 3;
    const int ld4 = lane >> 2;
    const int mg  = wid & 3;
    const int ng  = wid >> 2;

    float D[2][8][4];
#pragma unroll
    for (int s = 0; s < 2; s++)
#pragma unroll
        for (int n = 0; n < 8; n++)
#pragma unroll
            for (int i = 0; i < 4; i++) D[s][n][i] = 0.f;

    for (int cc = 0; cc < 8; cc++) {
        __syncthreads();      // all warps done reading previous patch
        for (int i = t; i < 32*4*66; i += 256) {
            int c   = i / 264;
            int rem = i - c*264;
            int r   = rem / 66;
            int col = rem - r*66;
            int y   = h0 - 1 + r;
            int xx  = col - 1;
            float v = 0.f;
            if (y >= 0 && y < HN && xx >= 0 && xx < WN)
                v = x[((b*CN + cc*32 + c)*HN + y)*WN + xx];
            patch[c*264 + r*66 + col] = tf32r(v);
        }
        __syncthreads();

        for (int kk = 0; kk < KKN; kk++) {
            const float4* wf = (const float4*)(g_wA + (cc*9 + kk)*4096);
            const int ky = kk / 3, kx = kk - (kk/3)*3;
            const int rbase = (ng + ky)*66 + kx + ld4;
#pragma unroll
            for (int step = 0; step < 4; step++) {
                const int k0 = step*8;
                float4 af0 = wf[((mg*2 + 0)*4 + step)*32 + lane];
                float4 af1 = wf[((mg*2 + 1)*4 + step)*32 + lane];
                const int bb = (k0 + lm4)*264 + rbase;
#pragma unroll
                for (int nt = 0; nt < 8; nt++) {
                    uint32_t b0 = PU[bb + nt*8];
                    uint32_t b1 = PU[bb + nt*8 + 4*264];
                    mma_tf32(D[0][nt], __float_as_uint(af0.x), __float_as_uint(af0.y),
                             __float_as_uint(af0.z), __float_as_uint(af0.w), b0, b1);
                    mma_tf32(D[1][nt], __float_as_uint(af1.x), __float_as_uint(af1.y),
                             __float_as_uint(af1.z), __float_as_uint(af1.w), b0, b1);
                }
            }
        }
    }

    const int h = h0 + ng;
#pragma unroll
    for (int s = 0; s < 2; s++) {
#pragma unroll
        for (int nt = 0; nt < 8; nt++) {
            int ocA = mg*32 + s*16 + ld4;
            int ocB = ocA + 8;
            int w   = nt*8 + lm4*2;
            if (ocA < OCF) {
                float bo = b_off[ocA];
                *reinterpret_cast<float2*>(&g_off[((b*OCF + ocA)*HN + h)*WN + w])
                    = make_float2(D[s][nt][0] + bo, D[s][nt][1] + bo);
            }
            if (ocB < OCF) {
                float bo = b_off[ocB];
                *reinterpret_cast<float2*>(&g_off[((b*OCF + ocB)*HN + h)*WN + w])
                    = make_float2(D[s][nt][2] + bo, D[s][nt][3] + bo);
            }
        }
    }
}

// ---------------------------------------------------------------------------
// Kernel 2: deformable sampling + grouped conv; A fragments via LDG.128
// from g_wT, gather via g_xQ, S in smem.
// grid (HN/4, GN, BN), block 256. smem: S [64c][264] (67.6KB)
// ---------------------------------------------------------------------------
#define DCN_FLOATS (CG*264)

__global__ void __launch_bounds__(256, 2) dcn_mma_k(
    const float* __restrict__ b_dcn)
{
    extern __shared__ float sm[];
    float* S = sm;
    const uint32_t* SU = (const uint32_t*)S;

    const int h0 = blockIdx.x * 4;
    const int g  = blockIdx.y;
    const int b  = blockIdx.z;
    const int t  = threadIdx.x;
    const int wid = t >> 5;
    const int lane = t & 31;
    const int lm4 = lane & 3;
    const int ld4 = lane >> 2;
    const int mg  = wid & 1;
    const int ng  = wid >> 1;

    const int pxA = t;
    const int hA  = h0 + (t >> 6);
    const int wA  = t & 63;
    const float* xq = g_xQ + (size_t)(b*GN + g)*16*HWN*4;

    float D[2][8][4];
#pragma unroll
    for (int s = 0; s < 2; s++)
#pragma unroll
        for (int n = 0; n < 8; n++)
#pragma unroll
            for (int i = 0; i < 4; i++) D[s][n][i] = 0.f;

    for (int k = 0; k < KKN; k++) {
        __syncthreads();   // previous mma done reading S
        // ---- bilinear corner data (registers) ----
        int i0, i1, i2, i3; float w0, w1, w2, w3;
        {
            int ky = k / 3 - 1;
            int kx = k - (k/3)*3 - 1;
            int sp = hA*WN + wA;
            const float* ob = g_off + b*OCF*HWN;
            float oy = ob[((g*KKN + k)*2    )*HWN + sp];
            float ox = ob[((g*KKN + k)*2 + 1)*HWN + sp];
            float mz = ob[(2*GN*KKN + g*KKN + k)*HWN + sp];
            float mk = 1.f / (1.f + expf(-mz));
            float py  = (float)(hA + ky) + oy;
            float pxx = (float)(wA + kx) + ox;
            float y0f = floorf(py),  x0f = floorf(pxx);
            float wy1 = py - y0f,    wx1 = pxx - x0f;
            float wy0 = 1.f - wy1,   wx0 = 1.f - wx1;
            int y0 = (int)y0f, x0i = (int)x0f;
            int y1 = y0 + 1,   x1i = x0i + 1;
            bool vy0 = (y0 >= 0) & (y0 < HN);
            bool vy1 = (y1 >= 0) & (y1 < HN);
            bool vx0 = (x0i >= 0) & (x0i < WN);
            bool vx1 = (x1i >= 0) & (x1i < WN);
            int y0c = min(max(y0, 0), HN-1), y1c = min(max(y1, 0), HN-1);
            int x0c = min(max(x0i,0), WN-1), x1c = min(max(x1i,0), WN-1);
            i0 = y0c*WN + x0c;  i1 = y0c*WN + x1c;
            i2 = y1c*WN + x0c;  i3 = y1c*WN + x1c;
            w0 = (vy0 && vx0) ? wy0*wx0*mk : 0.f;
            w1 = (vy0 && vx1) ? wy0*wx1*mk : 0.f;
            w2 = (vy1 && vx0) ? wy1*wx0*mk : 0.f;
            w3 = (vy1 && vx1) ? wy1*wx1*mk : 0.f;
        }
        // ---- gather: 16 c4-chunks, 4 corner LDG.128 each (lane-coalesced) ----
#pragma unroll 4
        for (int c4 = 0; c4 < 16; c4++) {
            const float4* plane = (const float4*)(xq + (size_t)c4*HWN*4);
            float4 A = plane[i0], Bv = plane[i1], Cv = plane[i2], Dv = plane[i3];
            float* sc = S + (c4*4)*264 + pxA;
            sc[0]     = tf32r(w0*A.x + w1*Bv.x + w2*Cv.x + w3*Dv.x);
            sc[264]   = tf32r(w0*A.y + w1*Bv.y + w2*Cv.y + w3*Dv.y);
            sc[2*264] = tf32r(w0*A.z + w1*Bv.z + w2*Cv.z + w3*Dv.z);
            sc[3*264] = tf32r(w0*A.w + w1*Bv.w + w2*Cv.w + w3*Dv.w);
        }
        __syncthreads();

        // ---- mma: K=64 -> 8 k8-steps; A frags via LDG.128 ----
        const float4* wf = (const float4*)(g_wT + (g*KKN + k)*4096);
#pragma unroll
        for (int step = 0; step < 8; step++) {
            const int k0 = step*8;
            float4 af0 = wf[((mg*2 + 0)*8 + step)*32 + lane];
            float4 af1 = wf[((mg*2 + 1)*8 + step)*32 + lane];
            const int bb = (k0 + lm4)*264 + ng*64 + ld4;
#pragma unroll
            for (int nt = 0; nt < 8; nt++) {
                uint32_t b0 = SU[bb + nt*8];
                uint32_t b1 = SU[bb + nt*8 + 4*264];
                mma_tf32(D[0][nt], __float_as_uint(af0.x), __float_as_uint(af0.y),
                         __float_as_uint(af0.z), __float_as_uint(af0.w), b0, b1);
                mma_tf32(D[1][nt], __float_as_uint(af1.x), __float_as_uint(af1.y),
                         __float_as_uint(af1.z), __float_as_uint(af1.w), b0, b1);
            }
        }
    }

    // ---- epilogue: +bias, store ----
    const int h = h0 + ng;
#pragma unroll
    for (int s = 0; s < 2; s++) {
#pragma unroll
        for (int nt = 0; nt < 8; nt++) {
            int ocA = g*CG + mg*32 + s*16 + ld4;
            int ocB = ocA + 8;
            int w   = nt*8 + lm4*2;
            float boA = b_dcn[ocA], boB = b_dcn[ocB];
            *reinterpret_cast<float2*>(&g_out[((b*CN + ocA)*HN + h)*WN + w])
                = make_float2(D[s][nt][0] + boA, D[s][nt][1] + boA);
            *reinterpret_cast<float2*>(&g_out[((b*CN + ocB)*HN + h)*WN + w])
                = make_float2(D[s][nt][2] + boB, D[s][nt][3] + boB);
        }
    }
}

// ---------------------------------------------------------------------------
// Kernel 3: LayerNorm over C + sigmoid + gate — register-resident values.
// grid (HN*2, BN), block 256. Thread: 32 channels of one pixel.
// ---------------------------------------------------------------------------
__global__ void __launch_bounds__(256) ln_gate_k(
    const float* __restrict__ x, const float* __restrict__ gamma,
    const float* __restrict__ beta, float* __restrict__ out)
{
    __shared__ float rs[8][32];
    __shared__ float rq[8][32];
    __shared__ float smu[32], srinv[32];

    const int b    = blockIdx.y;
    const int h    = blockIdx.x >> 1;
    const int wseg = (blockIdx.x & 1) * 32;
    const int t    = threadIdx.x;
    const int gi   = t >> 5;
    const int lane = t & 31;
    const int base = b*CN*HWN + h*WN + wseg + lane;

    const float* src = g_out + base + gi*32*HWN;
    float v[32];
    float s = 0.f, q = 0.f;
#pragma unroll
    for (int cc = 0; cc < 32; cc++) {
        float vv = src[cc*HWN];
        v[cc] = vv;
        s += vv; q += vv*vv;
    }
    rs[gi][lane] = s; rq[gi][lane] = q;
    __syncthreads();
    if (t < 32) {
        float ss = 0.f, qq = 0.f;
#pragma unroll
        for (int part = 0; part < 8; part++) { ss += rs[part][t]; qq += rq[part][t]; }
        float mu  = ss * (1.f/CN);
        float var = fmaxf(qq * (1.f/CN) - mu*mu, 0.f);
        smu[t]   = mu;
        srinv[t] = rsqrtf(var + 1e-5f);
    }
    __syncthreads();
    const float mu   = smu[lane];
    const float rinv = srinv[lane];
    const float* xp  = x + base + gi*32*HWN;
    float* op        = out + base + gi*32*HWN;
#pragma unroll
    for (int cc = 0; cc < 32; cc++) {
        int c = gi*32 + cc;
        float z = (v[cc] - mu) * rinv * gamma[c] + beta[c];
        float a = 1.f / (1.f + expf(-z));
        op[cc*HWN] = xp[cc*HWN] * a;
    }
}

// ---------------------------------------------------------------------------
// Entry point
// ---------------------------------------------------------------------------
extern "C" void kernel_launch(void* const* d_in, const int* in_sizes, int n_in,
                              void* d_out, int out_size)
{
    const float* x     = (const float*)d_in[0];
    const float* w_off = (const float*)d_in[1];
    const float* b_off = (const float*)d_in[2];
    const float* w_dcn = (const float*)d_in[3];
    const float* b_dcn = (const float*)d_in[4];
    const float* gamma = (const float*)d_in[5];
    const float* beta  = (const float*)d_in[6];
    float* out = (float*)d_out;

    (void)in_sizes; (void)n_in; (void)out_size;

    cudaFuncSetAttribute(offset_conv_mma_k, cudaFuncAttributeMaxDynamicSharedMemorySize,
                         OFC_FLOATS * (int)sizeof(float));
    cudaFuncSetAttribute(dcn_mma_k, cudaFuncAttributeMaxDynamicSharedMemorySize,
                         DCN_FLOATS * (int)sizeof(float));

    prep_wT_k<<<(GN*KKN*4096 + 255)/256, 256>>>(w_dcn);
    prep_wA_k<<<(8*KKN*4096 + 255)/256, 256>>>(w_off);
    build_xQ_k<<<dim3(HWN/256, 16, BN*GN), 256>>>(x);
    offset_conv_mma_k<<<dim3(HN/2, BN), 256, OFC_FLOATS * sizeof(float)>>>(x, b_off);
    dcn_mma_k<<<dim3(HN/4, GN, BN), 256, DCN_FLOATS * sizeof(float)>>>(b_dcn);
    ln_gate_k<<<dim3(HN*2, BN), 256>>>(x, gamma, beta, out);
}

// round 9
// speedup vs baseline: 1.7853x; 1.0625x over previous
#include <cuda_runtime.h>
#include <cstdint>

// Problem constants
#define BN   8
#define CN   256
#define HN   64
#define WN   64
#define GN   4
#define KKN  9
#define CG   64
#define OCF  108
#define OCP  128
#define HWN  (HN*WN)

// ---------------------------------------------------------------------------
// Scratch
// ---------------------------------------------------------------------------
__device__ float g_off[BN*OCF*HWN];          // offset/mask conv output
__device__ float g_out[BN*CN*HWN];           // DCN conv output (pre-LN)
__device__ float g_wT [GN*KKN*4096];         // w_dcn fragment-baked per tile
__device__ float g_wA [8*KKN*4096];          // w_off fragment-baked per tile
__device__ float g_xQ [BN*GN*16*HWN*4];      // x 4-ch interleave: [b][g][c4][px][4]

// ---------------------------------------------------------------------------
// helpers
// ---------------------------------------------------------------------------
__device__ __forceinline__ float tf32r(float v) {
    uint32_t u; asm("cvt.rna.tf32.f32 %0, %1;" : "=r"(u) : "f"(v));
    return __uint_as_float(u);
}
__device__ __forceinline__ void mma_tf32(float* d, uint32_t a0, uint32_t a1,
                                         uint32_t a2, uint32_t a3,
                                         uint32_t b0, uint32_t b1) {
    asm volatile(
        "mma.sync.aligned.m16n8k8.row.col.f32.tf32.tf32.f32 "
        "{%0,%1,%2,%3}, {%4,%5,%6,%7}, {%8,%9}, {%0,%1,%2,%3};"
        : "+f"(d[0]), "+f"(d[1]), "+f"(d[2]), "+f"(d[3])
        : "r"(a0), "r"(a1), "r"(a2), "r"(a3), "r"(b0), "r"(b1));
}

// ---------------------------------------------------------------------------
// Kernel 0a: w_dcn -> g_wT fragment-baked.
// tile = g*9+k (4096 floats): [(mt*8+step)*32 + lane][r], r=0..3:
//   oc = mt*16 + (r&1)*8 + (lane>>2),  c = step*8 + (lane&3) + (r>>1)*4
// ---------------------------------------------------------------------------
__global__ void __launch_bounds__(256) prep_wT_k(const float* __restrict__ w_dcn)
{
    int i = blockIdx.x * 256 + threadIdx.x;
    if (i >= GN*KKN*4096) return;
    int tile = i >> 12;
    int r    = i & 3;
    int lane = (i >> 2) & 31;
    int fs   = (i >> 7) & 31;         // mt*8 + step
    int mt   = fs >> 3, step = fs & 7;
    int k    = tile % 9;
    int g    = tile / 9;
    int oc   = mt*16 + ((r & 1) << 3) + (lane >> 2);
    int c    = step*8 + (lane & 3) + ((r >> 1) << 2);
    g_wT[i] = tf32r(w_dcn[((g*CG + oc)*CG + c)*KKN + k]);
}

// ---------------------------------------------------------------------------
// Kernel 0b: w_off -> g_wA fragment-baked.
// tile = cc*9+kk: [(mt*4+step)*32 + lane][r]
// ---------------------------------------------------------------------------
__global__ void __launch_bounds__(256) prep_wA_k(const float* __restrict__ w_off)
{
    int i = blockIdx.x * 256 + threadIdx.x;
    if (i >= 8*KKN*4096) return;
    int tile = i >> 12;
    int r    = i & 3;
    int lane = (i >> 2) & 31;
    int fs   = (i >> 7) & 31;         // mt*4 + step
    int mt   = fs >> 2, step = fs & 3;
    int kk   = tile % 9;
    int cc   = tile / 9;
    int oc   = mt*16 + ((r & 1) << 3) + (lane >> 2);
    int c    = step*8 + (lane & 3) + ((r >> 1) << 2);
    float w = 0.f;
    if (oc < OCF) w = tf32r(w_off[(oc*CN + cc*32 + c)*KKN + kk]);
    g_wA[i] = w;
}

// ---------------------------------------------------------------------------
// Kernel 0c: build g_xQ[b][g][c4][px][4] from x [b][c][px].
// ---------------------------------------------------------------------------
__global__ void __launch_bounds__(256) build_xQ_k(const float* __restrict__ x)
{
    const int bg = blockIdx.z;
    const int c4 = blockIdx.y;
    const int px = blockIdx.x * 256 + threadIdx.x;
    const float* src = x + (size_t)bg*CG*HWN + c4*4*HWN + px;
    float4 v;
    v.x = src[0];
    v.y = src[HWN];
    v.z = src[2*HWN];
    v.w = src[3*HWN];
    *reinterpret_cast<float4*>(g_xQ + ((size_t)(bg*16 + c4)*HWN + px)*4) = v;
}

// ---------------------------------------------------------------------------
// Kernel 1: offset/mask conv; warp tile 64oc x 32px (4 m-tiles x 4 n-tiles).
// grid (HN/2, BN), block 256 (8 warps): mg = wid&1 (oc half), ng = wid>>1:
//   row = ng>>1, colhalf = ng&1.
// smem: patch [32c][4r][66] pitch264 (33.8KB)
// ---------------------------------------------------------------------------
#define OFC_FLOATS 8448

__global__ void __launch_bounds__(256, 2) offset_conv_mma_k(
    const float* __restrict__ x, const float* __restrict__ b_off)
{
    extern __shared__ float sm[];
    float* patch = sm;
    const uint32_t* PU = (const uint32_t*)patch;

    const int h0  = blockIdx.x * 2;
    const int b   = blockIdx.y;
    const int t   = threadIdx.x;
    const int wid = t >> 5;
    const int lane = t & 31;
    const int lm4 = lane & 3;
    const int ld4 = lane >> 2;
    const int mg  = wid & 1;          // oc half: mg*64
    const int ng  = wid >> 1;         // 0..3
    const int row = ng >> 1;          // px row within block (0/1)
    const int ch  = ng & 1;           // col half: ch*32

    float D[4][4][4];
#pragma unroll
    for (int s = 0; s < 4; s++)
#pragma unroll
        for (int n = 0; n < 4; n++)
#pragma unroll
            for (int i = 0; i < 4; i++) D[s][n][i] = 0.f;

    for (int cc = 0; cc < 8; cc++) {
        __syncthreads();      // all warps done reading previous patch
        for (int i = t; i < 32*4*66; i += 256) {
            int c   = i / 264;
            int rem = i - c*264;
            int r   = rem / 66;
            int col = rem - r*66;
            int y   = h0 - 1 + r;
            int xx  = col - 1;
            float v = 0.f;
            if (y >= 0 && y < HN && xx >= 0 && xx < WN)
                v = x[((b*CN + cc*32 + c)*HN + y)*WN + xx];
            patch[c*264 + r*66 + col] = tf32r(v);
        }
        __syncthreads();

        for (int kk = 0; kk < KKN; kk++) {
            const float4* wf = (const float4*)(g_wA + (cc*9 + kk)*4096);
            const int ky = kk / 3, kx = kk - (kk/3)*3;
            const int rbase = (row + ky)*66 + kx + ch*32 + ld4;
#pragma unroll
            for (int step = 0; step < 4; step++) {
                const int k0 = step*8;
                float4 af[4];
#pragma unroll
                for (int s = 0; s < 4; s++)
                    af[s] = wf[((mg*4 + s)*4 + step)*32 + lane];
                const int bb = (k0 + lm4)*264 + rbase;
#pragma unroll
                for (int nt = 0; nt < 4; nt++) {
                    uint32_t b0 = PU[bb + nt*8];
                    uint32_t b1 = PU[bb + nt*8 + 4*264];
#pragma unroll
                    for (int s = 0; s < 4; s++)
                        mma_tf32(D[s][nt], __float_as_uint(af[s].x), __float_as_uint(af[s].y),
                                 __float_as_uint(af[s].z), __float_as_uint(af[s].w), b0, b1);
                }
            }
        }
    }

    const int h = h0 + row;
#pragma unroll
    for (int s = 0; s < 4; s++) {
#pragma unroll
        for (int nt = 0; nt < 4; nt++) {
            int ocA = mg*64 + s*16 + ld4;
            int ocB = ocA + 8;
            int w   = ch*32 + nt*8 + lm4*2;
            if (ocA < OCF) {
                float bo = b_off[ocA];
                *reinterpret_cast<float2*>(&g_off[((b*OCF + ocA)*HN + h)*WN + w])
                    = make_float2(D[s][nt][0] + bo, D[s][nt][1] + bo);
            }
            if (ocB < OCF) {
                float bo = b_off[ocB];
                *reinterpret_cast<float2*>(&g_off[((b*OCF + ocB)*HN + h)*WN + w])
                    = make_float2(D[s][nt][2] + bo, D[s][nt][3] + bo);
            }
        }
    }
}

// ---------------------------------------------------------------------------
// Kernel 2: deformable sampling + grouped conv; warp tile 64oc x 32px.
// grid (HN/4, GN, BN), block 256 (8 warps): ng = wid, px chunk ng*32.
// smem: S [64c][264] (67.6KB)
// ---------------------------------------------------------------------------
#define DCN_FLOATS (CG*264)

__global__ void __launch_bounds__(256, 2) dcn_mma_k(
    const float* __restrict__ b_dcn)
{
    extern __shared__ float sm[];
    float* S = sm;
    const uint32_t* SU = (const uint32_t*)S;

    const int h0 = blockIdx.x * 4;
    const int g  = blockIdx.y;
    const int b  = blockIdx.z;
    const int t  = threadIdx.x;
    const int wid = t >> 5;
    const int lane = t & 31;
    const int lm4 = lane & 3;
    const int ld4 = lane >> 2;
    const int ng  = wid;              // px chunk: ng*32

    const int pxA = t;
    const int hA  = h0 + (t >> 6);
    const int wA  = t & 63;
    const float* xq = g_xQ + (size_t)(b*GN + g)*16*HWN*4;

    float D[4][4][4];
#pragma unroll
    for (int s = 0; s < 4; s++)
#pragma unroll
        for (int n = 0; n < 4; n++)
#pragma unroll
            for (int i = 0; i < 4; i++) D[s][n][i] = 0.f;

    for (int k = 0; k < KKN; k++) {
        __syncthreads();   // previous mma done reading S
        // ---- bilinear corner data (registers) ----
        int i0, i1, i2, i3; float w0, w1, w2, w3;
        {
            int ky = k / 3 - 1;
            int kx = k - (k/3)*3 - 1;
            int sp = hA*WN + wA;
            const float* ob = g_off + b*OCF*HWN;
            float oy = ob[((g*KKN + k)*2    )*HWN + sp];
            float ox = ob[((g*KKN + k)*2 + 1)*HWN + sp];
            float mz = ob[(2*GN*KKN + g*KKN + k)*HWN + sp];
            float mk = 1.f / (1.f + expf(-mz));
            float py  = (float)(hA + ky) + oy;
            float pxx = (float)(wA + kx) + ox;
            float y0f = floorf(py),  x0f = floorf(pxx);
            float wy1 = py - y0f,    wx1 = pxx - x0f;
            float wy0 = 1.f - wy1,   wx0 = 1.f - wx1;
            int y0 = (int)y0f, x0i = (int)x0f;
            int y1 = y0 + 1,   x1i = x0i + 1;
            bool vy0 = (y0 >= 0) & (y0 < HN);
            bool vy1 = (y1 >= 0) & (y1 < HN);
            bool vx0 = (x0i >= 0) & (x0i < WN);
            bool vx1 = (x1i >= 0) & (x1i < WN);
            int y0c = min(max(y0, 0), HN-1), y1c = min(max(y1, 0), HN-1);
            int x0c = min(max(x0i,0), WN-1), x1c = min(max(x1i,0), WN-1);
            i0 = y0c*WN + x0c;  i1 = y0c*WN + x1c;
            i2 = y1c*WN + x0c;  i3 = y1c*WN + x1c;
            w0 = (vy0 && vx0) ? wy0*wx0*mk : 0.f;
            w1 = (vy0 && vx1) ? wy0*wx1*mk : 0.f;
            w2 = (vy1 && vx0) ? wy1*wx0*mk : 0.f;
            w3 = (vy1 && vx1) ? wy1*wx1*mk : 0.f;
        }
        // ---- gather: 16 c4-chunks, 4 corner LDG.128 each (lane-coalesced) ----
#pragma unroll 4
        for (int c4 = 0; c4 < 16; c4++) {
            const float4* plane = (const float4*)(xq + (size_t)c4*HWN*4);
            float4 A = plane[i0], Bv = plane[i1], Cv = plane[i2], Dv = plane[i3];
            float* sc = S + (c4*4)*264 + pxA;
            sc[0]     = tf32r(w0*A.x + w1*Bv.x + w2*Cv.x + w3*Dv.x);
            sc[264]   = tf32r(w0*A.y + w1*Bv.y + w2*Cv.y + w3*Dv.y);
            sc[2*264] = tf32r(w0*A.z + w1*Bv.z + w2*Cv.z + w3*Dv.z);
            sc[3*264] = tf32r(w0*A.w + w1*Bv.w + w2*Cv.w + w3*Dv.w);
        }
        __syncthreads();

        // ---- mma: K=64 -> 8 k8-steps; A frags via LDG.128, all 4 m-tiles ----
        const float4* wf = (const float4*)(g_wT + (g*KKN + k)*4096);
#pragma unroll
        for (int step = 0; step < 8; step++) {
            const int k0 = step*8;
            float4 af[4];
#pragma unroll
            for (int s = 0; s < 4; s++)
                af[s] = wf[(s*8 + step)*32 + lane];
            const int bb = (k0 + lm4)*264 + ng*32 + ld4;
#pragma unroll
            for (int nt = 0; nt < 4; nt++) {
                uint32_t b0 = SU[bb + nt*8];
                uint32_t b1 = SU[bb + nt*8 + 4*264];
#pragma unroll
                for (int s = 0; s < 4; s++)
                    mma_tf32(D[s][nt], __float_as_uint(af[s].x), __float_as_uint(af[s].y),
                             __float_as_uint(af[s].z), __float_as_uint(af[s].w), b0, b1);
            }
        }
    }

    // ---- epilogue: +bias, store ----
    const int h = h0 + (ng >> 1);
#pragma unroll
    for (int s = 0; s < 4; s++) {
#pragma unroll
        for (int nt = 0; nt < 4; nt++) {
            int ocA = g*CG + s*16 + ld4;
            int ocB = ocA + 8;
            int w   = (ng & 1)*32 + nt*8 + lm4*2;
            float boA = b_dcn[ocA], boB = b_dcn[ocB];
            *reinterpret_cast<float2*>(&g_out[((b*CN + ocA)*HN + h)*WN + w])
                = make_float2(D[s][nt][0] + boA, D[s][nt][1] + boA);
            *reinterpret_cast<float2*>(&g_out[((b*CN + ocB)*HN + h)*WN + w])
                = make_float2(D[s][nt][2] + boB, D[s][nt][3] + boB);
        }
    }
}

// ---------------------------------------------------------------------------
// Kernel 3: LayerNorm over C + sigmoid + gate — register-resident values.
// ---------------------------------------------------------------------------
__global__ void __launch_bounds__(256) ln_gate_k(
    const float* __restrict__ x, const float* __restrict__ gamma,
    const float* __restrict__ beta, float* __restrict__ out)
{
    __shared__ float rs[8][32];
    __shared__ float rq[8][32];
    __shared__ float smu[32], srinv[32];

    const int b    = blockIdx.y;
    const int h    = blockIdx.x >> 1;
    const int wseg = (blockIdx.x & 1) * 32;
    const int t    = threadIdx.x;
    const int gi   = t >> 5;
    const int lane = t & 31;
    const int base = b*CN*HWN + h*WN + wseg + lane;

    const float* src = g_out + base + gi*32*HWN;
    float v[32];
    float s = 0.f, q = 0.f;
#pragma unroll
    for (int cc = 0; cc < 32; cc++) {
        float vv = src[cc*HWN];
        v[cc] = vv;
        s += vv; q += vv*vv;
    }
    rs[gi][lane] = s; rq[gi][lane] = q;
    __syncthreads();
    if (t < 32) {
        float ss = 0.f, qq = 0.f;
#pragma unroll
        for (int part = 0; part < 8; part++) { ss += rs[part][t]; qq += rq[part][t]; }
        float mu  = ss * (1.f/CN);
        float var = fmaxf(qq * (1.f/CN) - mu*mu, 0.f);
        smu[t]   = mu;
        srinv[t] = rsqrtf(var + 1e-5f);
    }
    __syncthreads();
    const float mu   = smu[lane];
    const float rinv = srinv[lane];
    const float* xp  = x + base + gi*32*HWN;
    float* op        = out + base + gi*32*HWN;
#pragma unroll
    for (int cc = 0; cc < 32; cc++) {
        int c = gi*32 + cc;
        float z = (v[cc] - mu) * rinv * gamma[c] + beta[c];
        float a = 1.f / (1.f + expf(-z));
        op[cc*HWN] = xp[cc*HWN] * a;
    }
}

// ---------------------------------------------------------------------------
// Entry point
// ---------------------------------------------------------------------------
extern "C" void kernel_launch(void* const* d_in, const int* in_sizes, int n_in,
                              void* d_out, int out_size)
{
    const float* x     = (const float*)d_in[0];
    const float* w_off = (const float*)d_in[1];
    const float* b_off = (const float*)d_in[2];
    const float* w_dcn = (const float*)d_in[3];
    const float* b_dcn = (const float*)d_in[4];
    const float* gamma = (const float*)d_in[5];
    const float* beta  = (const float*)d_in[6];
    float* out = (float*)d_out;

    (void)in_sizes; (void)n_in; (void)out_size;

    cudaFuncSetAttribute(offset_conv_mma_k, cudaFuncAttributeMaxDynamicSharedMemorySize,
                         OFC_FLOATS * (int)sizeof(float));
    cudaFuncSetAttribute(dcn_mma_k, cudaFuncAttributeMaxDynamicSharedMemorySize,
                         DCN_FLOATS * (int)sizeof(float));

    prep_wT_k<<<(GN*KKN*4096 + 255)/256, 256>>>(w_dcn);
    prep_wA_k<<<(8*KKN*4096 + 255)/256, 256>>>(w_off);
    build_xQ_k<<<dim3(HWN/256, 16, BN*GN), 256>>>(x);
    offset_conv_mma_k<<<dim3(HN/2, BN), 256, OFC_FLOATS * sizeof(float)>>>(x, b_off);
    dcn_mma_k<<<dim3(HN/4, GN, BN), 256, DCN_FLOATS * sizeof(float)>>>(b_dcn);
    ln_gate_k<<<dim3(HN*2, BN), 256>>>(x, gamma, beta, out);
}